// round 8
// baseline (speedup 1.0000x reference)
#include <cuda_runtime.h>
#include <math_constants.h>

// D_KNN soft-kNN imputation — single fused persistent-ish kernel.
//   inputs: X_train [N,64] f32, y_train [N,64] f32, X_missing [64] f32
//   output: [1,64] f32
//
// Each block: stream its share of X (contiguous 512B per LDG.128: 2 rows/LDG),
// per-warp register top-32 (ballot prefilter + shfl insert), bitonic epilogue
// -> sorted per-block top-32 + partial Z -> global. Last block to arrive merges
// all 592 sorted lists (prefetch + 1-compare skip), gathers y rows, emits.

#define NB1  592         // 4 blocks/SM on 148 SMs
#define T1   256
#define NWRP (T1 / 32)
#define KSEL 32
#define DIMS 64

typedef unsigned long long u64;
typedef unsigned int u32;

__device__ u64   g_btop[NB1 * KSEL];
__device__ float g_bz[NB1];
__device__ int   g_count = 0;     // last-block election; self-resets each run

// ---- warp-collective helpers ----

// Replace warp-max-held key with cand (caller guarantees cand < current max).
// Lexicographic (value, lane) argmax so sentinel ties converge to ONE lane.
__device__ __forceinline__ void winsert(u64& held, u32& mhi, u64 cand, int lane) {
    u64 v = held; int l = lane;
    #pragma unroll
    for (int off = 16; off; off >>= 1) {
        u64 ov = __shfl_xor_sync(0xffffffffu, v, off);
        int ol = __shfl_xor_sync(0xffffffffu, l, off);
        if (ov > v || (ov == v && ol > l)) { v = ov; l = ol; }
    }
    if (lane == l) held = cand;
    u64 v2 = held;
    #pragma unroll
    for (int off = 16; off; off >>= 1) {
        u64 ov = __shfl_xor_sync(0xffffffffu, v2, off);
        if (ov > v2) v2 = ov;
    }
    mhi = (u32)(v2 >> 32);
}

__device__ __forceinline__ u64 bsort32(u64 key, int lane) {
    #pragma unroll
    for (int k = 2; k <= 32; k <<= 1) {
        #pragma unroll
        for (int j = k >> 1; j; j >>= 1) {
            u64 p = __shfl_xor_sync(0xffffffffu, key, j);
            bool keepMin = (((lane & j) == 0) == ((lane & k) == 0));
            key = keepMin ? (key < p ? key : p) : (key > p ? key : p);
        }
    }
    return key;
}

__device__ __forceinline__ u64 bmerge32(u64 key, int lane) {
    #pragma unroll
    for (int j = 16; j; j >>= 1) {
        u64 p = __shfl_xor_sync(0xffffffffu, key, j);
        key = ((lane & j) == 0) ? (key < p ? key : p) : (key > p ? key : p);
    }
    return key;
}

// Merge two sorted ascending 32-lists -> sorted 32 smallest of the union.
__device__ __forceinline__ u64 merge_sorted(u64 a, u64 b, int lane) {
    u64 br = __shfl_sync(0xffffffffu, b, 31 - lane);
    a = (a < br) ? a : br;
    return bmerge32(a, lane);
}

__device__ __forceinline__ float dist4(float4 x, float4 qc) {
    float t, ss = 0.0f;
    t = x.x - qc.x; ss = fmaf(t, t, ss);
    t = x.y - qc.y; ss = fmaf(t, t, ss);
    t = x.z - qc.z; ss = fmaf(t, t, ss);
    t = x.w - qc.w; ss = fmaf(t, t, ss);
    return ss;
}

__global__ void __launch_bounds__(T1)
knn_fused(const float* __restrict__ X, const float* __restrict__ Y,
          const float* __restrict__ q, float* __restrict__ out, int N) {
    __shared__ u64 s_lists[NWRP][KSEL];
    __shared__ float s_z[NWRP];
    __shared__ float wv[KSEL];
    __shared__ int   iv[KSEL];
    __shared__ float zinv_s;
    __shared__ int amLast;

    const int tid  = threadIdx.x;
    const int lane = tid & 31;
    const int warp = tid >> 5;
    const int h    = lane >> 4;   // which of 2 rows this LDG
    const int c    = lane & 15;   // 16B column: contiguous 512B per LDG.128
    const int gw   = blockIdx.x * NWRP + warp;
    const int nw   = NB1 * NWRP;

    const float4 qc = __ldg((const float4*)q + c);

    u64 held = ~0ull;
    u32 mhi  = 0xFFFFFFFFu;
    float wsum = 0.0f;

    for (int base = gw * 8; base < N; base += nw * 8) {
        float4 x[4];
        #pragma unroll
        for (int j = 0; j < 4; j++) {
            const int rc = min(base + 2 * j + h, N - 1);
            x[j] = __ldg((const float4*)(X + (size_t)rc * DIMS) + c);
        }
        float ss[4];
        #pragma unroll
        for (int j = 0; j < 4; j++) ss[j] = dist4(x[j], qc);
        #pragma unroll
        for (int j = 0; j < 4; j++) {
            ss[j] += __shfl_xor_sync(0xffffffffu, ss[j], 1);
            ss[j] += __shfl_xor_sync(0xffffffffu, ss[j], 2);
            ss[j] += __shfl_xor_sync(0xffffffffu, ss[j], 4);
            ss[j] += __shfl_xor_sync(0xffffffffu, ss[j], 8);
        }
        u32 db[4];
        #pragma unroll
        for (int j = 0; j < 4; j++) {
            float d = sqrtf(ss[j]);
            if (base + 2 * j + h >= N) d = CUDART_INF_F;
            wsum += __expf(-d);            // each row counted 16x; /16 at end
            db[j] = __float_as_uint(d);
        }
        const u32 m = min(min(db[0], db[1]), min(db[2], db[3]));
        if (__ballot_sync(0xffffffffu, m < mhi)) {   // warp-uniform, rare
            #pragma unroll
            for (int j = 0; j < 4; j++) {
                const unsigned bal = __ballot_sync(0xffffffffu, db[j] < mhi);
                if (bal & 1u) {
                    const u32 dv = __shfl_sync(0xffffffffu, db[j], 0);
                    if (dv < mhi)
                        winsert(held, mhi, ((u64)dv << 32) | (u32)(base + 2 * j), lane);
                }
                if (bal & (1u << 16)) {
                    const u32 dv = __shfl_sync(0xffffffffu, db[j], 16);
                    if (dv < mhi)
                        winsert(held, mhi, ((u64)dv << 32) | (u32)(base + 2 * j + 1), lane);
                }
            }
        }
    }

    // ---- per-block epilogue: sorted top-32 + partial Z ----
    held = bsort32(held, lane);
    s_lists[warp][lane] = held;
    #pragma unroll
    for (int off = 16; off; off >>= 1) wsum += __shfl_xor_sync(0xffffffffu, wsum, off);
    if (lane == 0) s_z[warp] = wsum;
    __syncthreads();

    if (warp == 0) {
        u64 a = s_lists[0][lane];
        #pragma unroll
        for (int w = 1; w < NWRP; w++) a = merge_sorted(a, s_lists[w][lane], lane);
        g_btop[blockIdx.x * KSEL + lane] = a;
        if (lane == 0) {
            float z = 0.0f;
            #pragma unroll
            for (int w = 0; w < NWRP; w++) z += s_z[w];
            g_bz[blockIdx.x] = z * 0.0625f;   // /16
        }
    }

    // ---- last-block election ----
    __threadfence();
    __syncthreads();
    if (tid == 0) amLast = (atomicAdd(&g_count, 1) == NB1 - 1);
    __syncthreads();
    if (!amLast) return;
    if (tid == 0) g_count = 0;   // reset for next graph replay

    // ---- final merge: 8 warps x 74 sorted lists, prefetch + 1-compare skip ----
    u64 held2 = g_btop[warp * KSEL + lane];
    u64 hmax = __shfl_sync(0xffffffffu, held2, 31);
    u64 e = (warp + NWRP < NB1) ? g_btop[(warp + NWRP) * KSEL + lane] : ~0ull;
    for (int b = warp + NWRP; b < NB1; b += NWRP) {
        const int bn = b + NWRP;
        const u64 e_next = (bn < NB1) ? g_btop[bn * KSEL + lane] : ~0ull;
        const u64 bmin = __shfl_sync(0xffffffffu, e, 0);
        if (bmin < hmax) {
            held2 = merge_sorted(held2, e, lane);
            hmax = __shfl_sync(0xffffffffu, held2, 31);
        }
        e = e_next;
    }
    s_lists[warp][lane] = held2;

    float z = 0.0f;
    for (int i = tid; i < NB1; i += T1) z += g_bz[i];
    #pragma unroll
    for (int off = 16; off; off >>= 1) z += __shfl_xor_sync(0xffffffffu, z, off);
    if (lane == 0) s_z[warp] = z;
    __syncthreads();

    if (warp == 0) {
        u64 a = s_lists[0][lane];
        #pragma unroll
        for (int w = 1; w < NWRP; w++) a = merge_sorted(a, s_lists[w][lane], lane);
        if (a == ~0ull) { wv[lane] = 0.0f; iv[lane] = 0; }
        else {
            wv[lane] = __expf(-__uint_as_float((u32)(a >> 32)));
            iv[lane] = (int)(u32)a;
        }
        if (lane == 0) {
            float t = 0.0f;
            #pragma unroll
            for (int w = 0; w < NWRP; w++) t += s_z[w];
            zinv_s = 1.0f / t;
        }
    }
    __syncthreads();

    if (tid < DIMS) {
        float acc = 0.0f;
        #pragma unroll
        for (int k = 0; k < KSEL; k++)
            acc += wv[k] * __ldg(Y + (size_t)iv[k] * DIMS + tid);
        out[tid] = acc * zinv_s;
    }
}

extern "C" void kernel_launch(void* const* d_in, const int* in_sizes, int n_in,
                              void* d_out, int out_size) {
    const float* X = (const float*)d_in[0];
    const float* Y = (const float*)d_in[1];
    const float* q = (const float*)d_in[2];
    float* out = (float*)d_out;
    const int N = in_sizes[0] / DIMS;

    knn_fused<<<NB1, T1>>>(X, Y, q, out, N);
}

// round 9
// speedup vs baseline: 1.1932x; 1.1932x over previous
#include <cuda_runtime.h>
#include <math_constants.h>

// D_KNN soft-kNN imputation — persistent fused kernel, smem-staged rows.
//   inputs: X_train [N,64] f32, y_train [N,64] f32, X_missing [64] f32
//   output: [1,64] f32
//
// 148 blocks x 256 threads. cp.async double-buffered 64KB tiles (256 rows).
// One thread = one row: full distance from smem (conflict-free padded layout),
// scalar threshold test, one ballot per 32 rows; rare shfl-inserts maintain a
// per-warp register top-32. Bitonic epilogue -> sorted per-block top-32 + Z.
// Last block merges 148 sorted lists and emits the weighted y sum.

#define NBLK 148
#define T1   256
#define NWRP (T1 / 32)
#define KSEL 32
#define DIMS 64
#define ROWS 256                 // rows per tile
#define PADF4 17                 // float4s per row in smem (padding: bank-safe)
#define TILE_F4 (ROWS * PADF4)

typedef unsigned long long u64;
typedef unsigned int u32;

__device__ u64   g_btop[NBLK * KSEL];
__device__ float g_bz[NBLK];
__device__ int   g_count = 0;    // last-block election; self-resets

// ---- warp-collective helpers ----

__device__ __forceinline__ void winsert(u64& held, u32& mhi, u64 cand, int lane) {
    u64 v = held; int l = lane;
    #pragma unroll
    for (int off = 16; off; off >>= 1) {
        u64 ov = __shfl_xor_sync(0xffffffffu, v, off);
        int ol = __shfl_xor_sync(0xffffffffu, l, off);
        if (ov > v || (ov == v && ol > l)) { v = ov; l = ol; }
    }
    if (lane == l) held = cand;
    u64 v2 = held;
    #pragma unroll
    for (int off = 16; off; off >>= 1) {
        u64 ov = __shfl_xor_sync(0xffffffffu, v2, off);
        if (ov > v2) v2 = ov;
    }
    mhi = (u32)(v2 >> 32);
}

__device__ __forceinline__ u64 bsort32(u64 key, int lane) {
    #pragma unroll
    for (int k = 2; k <= 32; k <<= 1) {
        #pragma unroll
        for (int j = k >> 1; j; j >>= 1) {
            u64 p = __shfl_xor_sync(0xffffffffu, key, j);
            bool keepMin = (((lane & j) == 0) == ((lane & k) == 0));
            key = keepMin ? (key < p ? key : p) : (key > p ? key : p);
        }
    }
    return key;
}

__device__ __forceinline__ u64 bmerge32(u64 key, int lane) {
    #pragma unroll
    for (int j = 16; j; j >>= 1) {
        u64 p = __shfl_xor_sync(0xffffffffu, key, j);
        key = ((lane & j) == 0) ? (key < p ? key : p) : (key > p ? key : p);
    }
    return key;
}

__device__ __forceinline__ u64 merge_sorted(u64 a, u64 b, int lane) {
    u64 br = __shfl_sync(0xffffffffu, b, 31 - lane);
    a = (a < br) ? a : br;
    return bmerge32(a, lane);
}

// ---- cp.async tile loader: 16 x 16B per thread, warp-contiguous 512B ----

__device__ __forceinline__ void issue_tile(const float* __restrict__ X,
                                           int tileBase, float4* buf,
                                           int tid, int N) {
    const u32 dstBase = (u32)__cvta_generic_to_shared(buf);
    const int c4 = tid & 15;            // float4 column within row
    const int r0 = tid >> 4;            // base row-in-tile
    #pragma unroll
    for (int k = 0; k < 16; k++) {
        const int rit = r0 + k * 16;
        const int grow = tileBase + rit;
        const float4* src = (const float4*)X + (size_t)min(grow, N - 1) * 16 + c4;
        const u32 dst = dstBase + (u32)(rit * PADF4 + c4) * 16u;
        asm volatile("cp.async.cg.shared.global [%0], [%1], 16;\n"
                     :: "r"(dst), "l"(src));
    }
}

__global__ void __launch_bounds__(T1, 1)
knn_fused(const float* __restrict__ X, const float* __restrict__ Y,
          const float* __restrict__ q, float* __restrict__ out, int N) {
    extern __shared__ float4 smem[];            // [2*TILE_F4] bufs + [16] q
    float4* qs = smem + 2 * TILE_F4;

    __shared__ u64 s_lists[NWRP][KSEL];
    __shared__ float s_z[NWRP];
    __shared__ float wv[KSEL];
    __shared__ int   iv[KSEL];
    __shared__ float zinv_s;
    __shared__ int amLast;

    const int tid  = threadIdx.x;
    const int lane = tid & 31;
    const int warp = tid >> 5;
    const int tilesTotal = (N + ROWS - 1) / ROWS;

    if (tid < 16) qs[tid] = __ldg((const float4*)q + tid);

    // prologue: prefetch first tile
    issue_tile(X, blockIdx.x * ROWS, smem, tid, N);
    asm volatile("cp.async.commit_group;\n" ::: "memory");

    u64 held = ~0ull;
    u32 mhi  = 0xFFFFFFFFu;
    float wsum = 0.0f;
    int cur = 0;

    for (int t = blockIdx.x; t < tilesTotal; t += NBLK) {
        const int tn = t + NBLK;
        if (tn < tilesTotal)
            issue_tile(X, tn * ROWS, smem + (cur ^ 1) * TILE_F4, tid, N);
        asm volatile("cp.async.commit_group;\n" ::: "memory");
        asm volatile("cp.async.wait_group 1;\n" ::: "memory");
        __syncthreads();

        // compute: this thread's row of the current tile
        const int grow = t * ROWS + tid;
        const float4* rp = smem + cur * TILE_F4 + tid * PADF4;
        float s0 = 0.f, s1 = 0.f, s2 = 0.f, s3 = 0.f;
        #pragma unroll
        for (int k = 0; k < 16; k += 4) {
            float4 x, qq; float d;
            x = rp[k + 0]; qq = qs[k + 0];
            d = x.x - qq.x; s0 = fmaf(d, d, s0);
            d = x.y - qq.y; s1 = fmaf(d, d, s1);
            d = x.z - qq.z; s2 = fmaf(d, d, s2);
            d = x.w - qq.w; s3 = fmaf(d, d, s3);
            x = rp[k + 1]; qq = qs[k + 1];
            d = x.x - qq.x; s0 = fmaf(d, d, s0);
            d = x.y - qq.y; s1 = fmaf(d, d, s1);
            d = x.z - qq.z; s2 = fmaf(d, d, s2);
            d = x.w - qq.w; s3 = fmaf(d, d, s3);
            x = rp[k + 2]; qq = qs[k + 2];
            d = x.x - qq.x; s0 = fmaf(d, d, s0);
            d = x.y - qq.y; s1 = fmaf(d, d, s1);
            d = x.z - qq.z; s2 = fmaf(d, d, s2);
            d = x.w - qq.w; s3 = fmaf(d, d, s3);
            x = rp[k + 3]; qq = qs[k + 3];
            d = x.x - qq.x; s0 = fmaf(d, d, s0);
            d = x.y - qq.y; s1 = fmaf(d, d, s1);
            d = x.z - qq.z; s2 = fmaf(d, d, s2);
            d = x.w - qq.w; s3 = fmaf(d, d, s3);
        }
        float dist = sqrtf((s0 + s1) + (s2 + s3));
        if (grow >= N) dist = CUDART_INF_F;
        wsum += __expf(-dist);                  // exp(-inf) = 0 for OOB
        const u32 db = __float_as_uint(dist);

        unsigned bal = __ballot_sync(0xffffffffu, db < mhi && grow < N);
        while (bal) {                            // warp-uniform, rare
            const int srcl = __ffs(bal) - 1;
            bal &= bal - 1;
            const u32 dv = __shfl_sync(0xffffffffu, db, srcl);
            const u32 ri = __shfl_sync(0xffffffffu, (u32)grow, srcl);
            if (dv < mhi) winsert(held, mhi, ((u64)dv << 32) | ri, lane);
        }
        __syncthreads();                         // done reading buf before reuse
        cur ^= 1;
    }

    // ---- per-block epilogue: sorted top-32 + partial Z ----
    held = bsort32(held, lane);
    s_lists[warp][lane] = held;
    #pragma unroll
    for (int off = 16; off; off >>= 1) wsum += __shfl_xor_sync(0xffffffffu, wsum, off);
    if (lane == 0) s_z[warp] = wsum;
    __syncthreads();

    if (warp == 0) {
        u64 a = s_lists[0][lane];
        #pragma unroll
        for (int w = 1; w < NWRP; w++) a = merge_sorted(a, s_lists[w][lane], lane);
        g_btop[blockIdx.x * KSEL + lane] = a;
        if (lane == 0) {
            float z = 0.0f;
            #pragma unroll
            for (int w = 0; w < NWRP; w++) z += s_z[w];
            g_bz[blockIdx.x] = z;
        }
    }

    // ---- last-block election ----
    __threadfence();
    __syncthreads();
    if (tid == 0) amLast = (atomicAdd(&g_count, 1) == NBLK - 1);
    __syncthreads();
    if (!amLast) return;
    if (tid == 0) g_count = 0;

    // ---- final merge: 8 warps x ~19 sorted lists, prefetch + 1-compare skip ----
    u64 held2 = g_btop[warp * KSEL + lane];
    u64 hmax = __shfl_sync(0xffffffffu, held2, 31);
    u64 e = (warp + NWRP < NBLK) ? g_btop[(warp + NWRP) * KSEL + lane] : ~0ull;
    for (int b = warp + NWRP; b < NBLK; b += NWRP) {
        const int bn = b + NWRP;
        const u64 e_next = (bn < NBLK) ? g_btop[bn * KSEL + lane] : ~0ull;
        const u64 bmin = __shfl_sync(0xffffffffu, e, 0);
        if (bmin < hmax) {
            held2 = merge_sorted(held2, e, lane);
            hmax = __shfl_sync(0xffffffffu, held2, 31);
        }
        e = e_next;
    }
    s_lists[warp][lane] = held2;

    float z = 0.0f;
    for (int i = tid; i < NBLK; i += T1) z += g_bz[i];
    #pragma unroll
    for (int off = 16; off; off >>= 1) z += __shfl_xor_sync(0xffffffffu, z, off);
    if (lane == 0) s_z[warp] = z;
    __syncthreads();

    if (warp == 0) {
        u64 a = s_lists[0][lane];
        #pragma unroll
        for (int w = 1; w < NWRP; w++) a = merge_sorted(a, s_lists[w][lane], lane);
        if (a == ~0ull) { wv[lane] = 0.0f; iv[lane] = 0; }
        else {
            wv[lane] = __expf(-__uint_as_float((u32)(a >> 32)));
            iv[lane] = (int)(u32)a;
        }
        if (lane == 0) {
            float t2 = 0.0f;
            #pragma unroll
            for (int w = 0; w < NWRP; w++) t2 += s_z[w];
            zinv_s = 1.0f / t2;
        }
    }
    __syncthreads();

    if (tid < DIMS) {
        float acc = 0.0f;
        #pragma unroll
        for (int k = 0; k < KSEL; k++)
            acc += wv[k] * __ldg(Y + (size_t)iv[k] * DIMS + tid);
        out[tid] = acc * zinv_s;
    }
}

extern "C" void kernel_launch(void* const* d_in, const int* in_sizes, int n_in,
                              void* d_out, int out_size) {
    const float* X = (const float*)d_in[0];
    const float* Y = (const float*)d_in[1];
    const float* q = (const float*)d_in[2];
    float* out = (float*)d_out;
    const int N = in_sizes[0] / DIMS;

    const int smemBytes = (2 * TILE_F4 + 16) * (int)sizeof(float4);  // ~139.5 KB
    cudaFuncSetAttribute(knn_fused, cudaFuncAttributeMaxDynamicSharedMemorySize,
                         smemBytes);
    knn_fused<<<NBLK, T1, smemBytes>>>(X, Y, q, out, N);
}

// round 10
// speedup vs baseline: 1.7693x; 1.4828x over previous
#include <cuda_runtime.h>
#include <math_constants.h>

// D_KNN soft-kNN imputation — persistent fused kernel, smem-staged rows.
//   inputs: X_train [N,64] f32, y_train [N,64] f32, X_missing [64] f32
//   output: [1,64] f32
//
// 444 blocks (3/SM) x 128 threads. cp.async double-buffered 32KB tiles
// (128 rows). One thread = one row from smem (padded, conflict-free).
// Selection: threshold compare + append to per-warp smem candidate buffer;
// bitonic sort+merge flush when >=32 pending (amortized ~30cyc/candidate,
// no warp-serial insert in the hot path). Last block merges 444 sorted
// lists and emits the weighted y sum.

#define NBLK 444
#define T1   128
#define NWRP (T1 / 32)
#define KSEL 32
#define DIMS 64
#define ROWS 128                 // rows per tile == T1
#define PADF4 17                 // float4s per row in smem (bank-safe padding)
#define TILE_F4 (ROWS * PADF4)

typedef unsigned long long u64;
typedef unsigned int u32;

__device__ u64   g_btop[NBLK * KSEL];
__device__ float g_bz[NBLK];
__device__ int   g_count = 0;    // last-block election; self-resets

// ---- warp-collective helpers ----

__device__ __forceinline__ u64 bsort32(u64 key, int lane) {
    #pragma unroll
    for (int k = 2; k <= 32; k <<= 1) {
        #pragma unroll
        for (int j = k >> 1; j; j >>= 1) {
            u64 p = __shfl_xor_sync(0xffffffffu, key, j);
            bool keepMin = (((lane & j) == 0) == ((lane & k) == 0));
            key = keepMin ? (key < p ? key : p) : (key > p ? key : p);
        }
    }
    return key;
}

__device__ __forceinline__ u64 bmerge32(u64 key, int lane) {
    #pragma unroll
    for (int j = 16; j; j >>= 1) {
        u64 p = __shfl_xor_sync(0xffffffffu, key, j);
        key = ((lane & j) == 0) ? (key < p ? key : p) : (key > p ? key : p);
    }
    return key;
}

// Merge two sorted ascending 32-lists -> sorted 32 smallest of the union.
__device__ __forceinline__ u64 merge_sorted(u64 a, u64 b, int lane) {
    u64 br = __shfl_sync(0xffffffffu, b, 31 - lane);
    a = (a < br) ? a : br;
    return bmerge32(a, lane);
}

// Flush the warp's candidate buffer (n <= 63) into sorted 'held'; update mhi.
__device__ __forceinline__ void flush_cands(volatile u64* wbuf, volatile int* wcnt,
                                            u64& held, u32& mhi, int lane) {
    __syncwarp();
    const int n = *wcnt;
    u64 c = (lane < n) ? wbuf[lane] : ~0ull;
    c = bsort32(c, lane);
    held = merge_sorted(held, c, lane);
    if (n > 32) {
        u64 c2 = (32 + lane < n) ? wbuf[32 + lane] : ~0ull;
        c2 = bsort32(c2, lane);
        held = merge_sorted(held, c2, lane);
    }
    __syncwarp();
    if (lane == 0) *wcnt = 0;
    __syncwarp();
    mhi = (u32)(__shfl_sync(0xffffffffu, held, 31) >> 32);
}

// ---- cp.async tile loader: 16 x 16B per thread, 2 contiguous rows/warp-op ----

__device__ __forceinline__ void issue_tile(const float* __restrict__ X,
                                           int tileBase, float4* buf,
                                           int tid, int N) {
    const u32 dstBase = (u32)__cvta_generic_to_shared(buf);
    const int c4 = tid & 15;
    const int r0 = tid >> 4;            // 0..7
    #pragma unroll
    for (int k = 0; k < 16; k++) {
        const int rit = r0 + k * 8;
        const int grow = tileBase + rit;
        const float4* src = (const float4*)X + (size_t)min(grow, N - 1) * 16 + c4;
        const u32 dst = dstBase + (u32)(rit * PADF4 + c4) * 16u;
        asm volatile("cp.async.cg.shared.global [%0], [%1], 16;\n"
                     :: "r"(dst), "l"(src));
    }
}

__global__ void __launch_bounds__(T1)
knn_fused(const float* __restrict__ X, const float* __restrict__ Y,
          const float* __restrict__ q, float* __restrict__ out, int N) {
    extern __shared__ float4 smem[];            // [2*TILE_F4] bufs + [16] q
    float4* qs = smem + 2 * TILE_F4;

    __shared__ u64 s_lists[NWRP][KSEL];
    __shared__ u64 wbuf[NWRP][64];              // per-warp candidate buffers
    __shared__ int wcnt[NWRP];
    __shared__ float s_z[NWRP];
    __shared__ float wv[KSEL];
    __shared__ int   iv[KSEL];
    __shared__ float zinv_s;
    __shared__ int amLast;

    const int tid  = threadIdx.x;
    const int lane = tid & 31;
    const int warp = tid >> 5;
    const int tilesTotal = (N + ROWS - 1) / ROWS;

    if (tid < 16) qs[tid] = __ldg((const float4*)q + tid);
    if (tid < NWRP) wcnt[tid] = 0;

    issue_tile(X, blockIdx.x * ROWS, smem, tid, N);
    asm volatile("cp.async.commit_group;\n" ::: "memory");

    u64 held = ~0ull;                            // sorted-ascending invariant
    u32 mhi  = 0xFFFFFFFFu;
    float wsum = 0.0f;
    int cur = 0;

    for (int t = blockIdx.x; t < tilesTotal; t += NBLK) {
        const int tn = t + NBLK;
        if (tn < tilesTotal)
            issue_tile(X, tn * ROWS, smem + (cur ^ 1) * TILE_F4, tid, N);
        asm volatile("cp.async.commit_group;\n" ::: "memory");
        asm volatile("cp.async.wait_group 1;\n" ::: "memory");
        __syncthreads();

        // compute: this thread's row of the current tile
        const int grow = t * ROWS + tid;
        const float4* rp = smem + cur * TILE_F4 + tid * PADF4;
        float s0 = 0.f, s1 = 0.f, s2 = 0.f, s3 = 0.f;
        #pragma unroll
        for (int k = 0; k < 16; k++) {
            const float4 x = rp[k];
            const float4 qq = qs[k];
            float d;
            d = x.x - qq.x; s0 = fmaf(d, d, s0);
            d = x.y - qq.y; s1 = fmaf(d, d, s1);
            d = x.z - qq.z; s2 = fmaf(d, d, s2);
            d = x.w - qq.w; s3 = fmaf(d, d, s3);
        }
        float dist = sqrtf((s0 + s1) + (s2 + s3));
        if (grow >= N) dist = CUDART_INF_F;
        wsum += __expf(-dist);                   // exp(-inf) = 0 for OOB
        const u32 db = __float_as_uint(dist);

        if (db < mhi && grow < N) {              // cheap append, no warp collective
            const int p = atomicAdd(&wcnt[warp], 1);
            wbuf[warp][p] = ((u64)db << 32) | (u32)grow;
        }
        __syncwarp();
        if (wcnt[warp] >= 32)                    // warp-uniform; rare
            flush_cands(wbuf[warp], &wcnt[warp], held, mhi, lane);

        __syncthreads();                         // buf fully read before reuse
        cur ^= 1;
    }
    if (wcnt[warp] > 0)
        flush_cands(wbuf[warp], &wcnt[warp], held, mhi, lane);

    // ---- per-block epilogue: sorted top-32 + partial Z ----
    s_lists[warp][lane] = held;                  // already sorted
    #pragma unroll
    for (int off = 16; off; off >>= 1) wsum += __shfl_xor_sync(0xffffffffu, wsum, off);
    if (lane == 0) s_z[warp] = wsum;
    __syncthreads();

    if (warp == 0) {
        u64 a = s_lists[0][lane];
        #pragma unroll
        for (int w = 1; w < NWRP; w++) a = merge_sorted(a, s_lists[w][lane], lane);
        g_btop[blockIdx.x * KSEL + lane] = a;
        if (lane == 0) {
            float z = 0.0f;
            #pragma unroll
            for (int w = 0; w < NWRP; w++) z += s_z[w];
            g_bz[blockIdx.x] = z;
        }
    }

    // ---- last-block election ----
    __threadfence();
    __syncthreads();
    if (tid == 0) amLast = (atomicAdd(&g_count, 1) == NBLK - 1);
    __syncthreads();
    if (!amLast) return;
    if (tid == 0) g_count = 0;

    // ---- final merge: 4 warps x 111 sorted lists, prefetch + 1-compare skip ----
    u64 held2 = g_btop[warp * KSEL + lane];
    u64 hmax = __shfl_sync(0xffffffffu, held2, 31);
    u64 e = (warp + NWRP < NBLK) ? g_btop[(warp + NWRP) * KSEL + lane] : ~0ull;
    for (int b = warp + NWRP; b < NBLK; b += NWRP) {
        const int bn = b + NWRP;
        const u64 e_next = (bn < NBLK) ? g_btop[bn * KSEL + lane] : ~0ull;
        const u64 bmin = __shfl_sync(0xffffffffu, e, 0);
        if (bmin < hmax) {
            held2 = merge_sorted(held2, e, lane);
            hmax = __shfl_sync(0xffffffffu, held2, 31);
        }
        e = e_next;
    }
    s_lists[warp][lane] = held2;

    float z = 0.0f;
    for (int i = tid; i < NBLK; i += T1) z += g_bz[i];
    #pragma unroll
    for (int off = 16; off; off >>= 1) z += __shfl_xor_sync(0xffffffffu, z, off);
    if (lane == 0) s_z[warp] = z;
    __syncthreads();

    if (warp == 0) {
        u64 a = s_lists[0][lane];
        #pragma unroll
        for (int w = 1; w < NWRP; w++) a = merge_sorted(a, s_lists[w][lane], lane);
        if (a == ~0ull) { wv[lane] = 0.0f; iv[lane] = 0; }
        else {
            wv[lane] = __expf(-__uint_as_float((u32)(a >> 32)));
            iv[lane] = (int)(u32)a;
        }
        if (lane == 0) {
            float t2 = 0.0f;
            #pragma unroll
            for (int w = 0; w < NWRP; w++) t2 += s_z[w];
            zinv_s = 1.0f / t2;
        }
    }
    __syncthreads();

    if (tid < DIMS) {
        float acc = 0.0f;
        #pragma unroll
        for (int k = 0; k < KSEL; k++)
            acc += wv[k] * __ldg(Y + (size_t)iv[k] * DIMS + tid);
        out[tid] = acc * zinv_s;
    }
}

extern "C" void kernel_launch(void* const* d_in, const int* in_sizes, int n_in,
                              void* d_out, int out_size) {
    const float* X = (const float*)d_in[0];
    const float* Y = (const float*)d_in[1];
    const float* q = (const float*)d_in[2];
    float* out = (float*)d_out;
    const int N = in_sizes[0] / DIMS;

    const int smemBytes = (2 * TILE_F4 + 16) * (int)sizeof(float4);  // ~68.3 KB
    cudaFuncSetAttribute(knn_fused, cudaFuncAttributeMaxDynamicSharedMemorySize,
                         smemBytes);
    knn_fused<<<NBLK, T1, smemBytes>>>(X, Y, q, out, N);
}

// round 13
// speedup vs baseline: 2.4075x; 1.3607x over previous
#include <cuda_runtime.h>
#include <math_constants.h>

// D_KNN soft-kNN imputation — persistent kernel, per-warp free-running pipelines.
//   inputs: X_train [N,64] f32, y_train [N,64] f32, X_missing [64] f32
//   output: [1,64] f32
//
// 444 blocks (3/SM) x 128 threads. Each WARP owns a private double-buffered
// 32-row (8.7KB) cp.async stream: issue -> commit -> wait_group 1 -> syncwarp
// -> compute. NO __syncthreads in the hot loop (kills the block convoy that
// pinned iteration latency at ~7.7K cyc). One thread = one row from padded
// smem. Selection: threshold + per-warp smem candidate buffer, bitonic flush.
// Two-tier last-block election merges 444 sorted lists with ~2us tail.

#define NBLK 444
#define T1   128
#define NWRP 4
#define GSZ  37                  // tier-1 group size (444 = 12*37)
#define NGRP 12
#define KSEL 32
#define DIMS 64
#define WROWS 32                 // rows per warp-tile
#define PADF4 17                 // float4s per row (bank-conflict-free)
#define WTILE_F4 (WROWS * PADF4) // 544 float4s = 8704 B

typedef unsigned long long u64;
typedef unsigned int u32;

__device__ u64   g_btop[NBLK * KSEL];
__device__ float g_bz[NBLK];
__device__ u64   g_gtop[NGRP * KSEL];
__device__ float g_gz[NGRP];
__device__ int   g_c1[NGRP];     // tier-1 counters (zero-init, self-reset)
__device__ int   g_c2 = 0;       // tier-2 counter

// ---- warp-collective helpers ----

__device__ __forceinline__ u64 bsort32(u64 key, int lane) {
    #pragma unroll
    for (int k = 2; k <= 32; k <<= 1) {
        #pragma unroll
        for (int j = k >> 1; j; j >>= 1) {
            u64 p = __shfl_xor_sync(0xffffffffu, key, j);
            bool keepMin = (((lane & j) == 0) == ((lane & k) == 0));
            key = keepMin ? (key < p ? key : p) : (key > p ? key : p);
        }
    }
    return key;
}

__device__ __forceinline__ u64 bmerge32(u64 key, int lane) {
    #pragma unroll
    for (int j = 16; j; j >>= 1) {
        u64 p = __shfl_xor_sync(0xffffffffu, key, j);
        key = ((lane & j) == 0) ? (key < p ? key : p) : (key > p ? key : p);
    }
    return key;
}

// Merge two sorted ascending 32-lists -> sorted 32 smallest of the union.
__device__ __forceinline__ u64 merge_sorted(u64 a, u64 b, int lane) {
    u64 br = __shfl_sync(0xffffffffu, b, 31 - lane);
    a = (a < br) ? a : br;
    return bmerge32(a, lane);
}

// Flush warp candidate buffer (n <= 63) into sorted 'held'; refresh mhi.
__device__ __forceinline__ void flush_cands(volatile u64* wbuf, volatile int* wcnt,
                                            u64& held, u32& mhi, int lane) {
    __syncwarp();
    const int n = *wcnt;
    u64 c = (lane < n) ? wbuf[lane] : ~0ull;
    c = bsort32(c, lane);
    held = merge_sorted(held, c, lane);
    if (n > 32) {
        u64 c2 = (32 + lane < n) ? wbuf[32 + lane] : ~0ull;
        c2 = bsort32(c2, lane);
        held = merge_sorted(held, c2, lane);
    }
    __syncwarp();
    if (lane == 0) *wcnt = 0;
    __syncwarp();
    mhi = (u32)(__shfl_sync(0xffffffffu, held, 31) >> 32);
}

// ---- per-warp cp.async loader: 16 x 16B per thread, 512B-contiguous ops ----

__device__ __forceinline__ void issue_wtile(const float* __restrict__ X,
                                            int rowBase, float4* buf,
                                            int lane, int N) {
    const u32 dstBase = (u32)__cvta_generic_to_shared(buf);
    const int c4 = lane & 15;
    const int h  = lane >> 4;
    #pragma unroll
    for (int k = 0; k < 16; k++) {
        const int rit = 2 * k + h;
        const float4* src = (const float4*)X
                          + (size_t)min(rowBase + rit, N - 1) * 16 + c4;
        const u32 dst = dstBase + (u32)(rit * PADF4 + c4) * 16u;
        asm volatile("cp.async.cg.shared.global [%0], [%1], 16;\n"
                     :: "r"(dst), "l"(src));
    }
}

__global__ void __launch_bounds__(T1)
knn_fused(const float* __restrict__ X, const float* __restrict__ Y,
          const float* __restrict__ q, float* __restrict__ out, int N) {
    extern __shared__ float4 smem[];     // [NWRP][2][WTILE_F4] + qs[16]
    float4* qs = smem + NWRP * 2 * WTILE_F4;

    __shared__ u64 s_lists[NWRP][KSEL];
    __shared__ u64 wbuf[NWRP][64];
    __shared__ int wcnt[NWRP];
    __shared__ float s_z[NWRP];
    __shared__ float wv[KSEL];
    __shared__ int   iv[KSEL];
    __shared__ float zinv_s;
    __shared__ int amLast1, amLast2;

    const int tid  = threadIdx.x;
    const int lane = tid & 31;
    const int warp = tid >> 5;
    const int tiles = (N + WROWS - 1) / WROWS;
    const int gw = blockIdx.x * NWRP + warp;
    const int stride = NBLK * NWRP;

    if (tid < 16) qs[tid] = __ldg((const float4*)q + tid);
    if (tid < NWRP) wcnt[tid] = 0;
    __syncthreads();                     // qs/wcnt visible; last block barrier in hot path

    float4* mybuf = smem + warp * 2 * WTILE_F4;

    if (gw < tiles) issue_wtile(X, gw * WROWS, mybuf, lane, N);
    asm volatile("cp.async.commit_group;\n" ::: "memory");

    u64 held = ~0ull;                    // sorted-ascending invariant
    u32 mhi  = 0xFFFFFFFFu;
    float wsum = 0.0f;
    int cur = 0;

    for (int t = gw; t < tiles; t += stride) {
        const int tn = t + stride;
        if (tn < tiles)
            issue_wtile(X, tn * WROWS, mybuf + (cur ^ 1) * WTILE_F4, lane, N);
        asm volatile("cp.async.commit_group;\n" ::: "memory");
        asm volatile("cp.async.wait_group 1;\n" ::: "memory");
        __syncwarp();                    // cross-lane visibility of landed tile

        const int grow = t * WROWS + lane;
        const float4* rp = mybuf + cur * WTILE_F4 + lane * PADF4;
        float s0 = 0.f, s1 = 0.f, s2 = 0.f, s3 = 0.f;
        #pragma unroll
        for (int k = 0; k < 16; k++) {
            const float4 x = rp[k];
            const float4 qq = qs[k];
            float d;
            d = x.x - qq.x; s0 = fmaf(d, d, s0);
            d = x.y - qq.y; s1 = fmaf(d, d, s1);
            d = x.z - qq.z; s2 = fmaf(d, d, s2);
            d = x.w - qq.w; s3 = fmaf(d, d, s3);
        }
        float dist = sqrtf((s0 + s1) + (s2 + s3));
        if (grow >= N) dist = CUDART_INF_F;
        wsum += __expf(-dist);
        const u32 db = __float_as_uint(dist);

        if (db < mhi && grow < N) {
            const int p = atomicAdd(&wcnt[warp], 1);
            wbuf[warp][p] = ((u64)db << 32) | (u32)grow;
        }
        __syncwarp();
        if (wcnt[warp] >= 32)            // warp-uniform; rare
            flush_cands(wbuf[warp], &wcnt[warp], held, mhi, lane);
        cur ^= 1;
    }
    if (wcnt[warp] > 0)
        flush_cands(wbuf[warp], &wcnt[warp], held, mhi, lane);

    // ---- per-block epilogue: sorted top-32 + partial Z ----
    s_lists[warp][lane] = held;
    #pragma unroll
    for (int off = 16; off; off >>= 1) wsum += __shfl_xor_sync(0xffffffffu, wsum, off);
    if (lane == 0) s_z[warp] = wsum;
    __syncthreads();

    if (warp == 0) {
        u64 a = s_lists[0][lane];
        #pragma unroll
        for (int w = 1; w < NWRP; w++) a = merge_sorted(a, s_lists[w][lane], lane);
        g_btop[blockIdx.x * KSEL + lane] = a;
        if (lane == 0) {
            float z = 0.0f;
            #pragma unroll
            for (int w = 0; w < NWRP; w++) z += s_z[w];
            g_bz[blockIdx.x] = z;
        }
    }

    // ---- tier-1 election: last block of each 37-block group ----
    const int gid = blockIdx.x / GSZ;
    const int b0  = gid * GSZ;
    __threadfence();
    __syncthreads();
    if (tid == 0) amLast1 = (atomicAdd(&g_c1[gid], 1) == GSZ - 1);
    __syncthreads();
    if (!amLast1) return;
    if (tid == 0) g_c1[gid] = 0;

    {   // merge this group's 37 sorted lists (4 warps, ~9 each, 1-compare skip)
        u64 h2 = g_btop[(b0 + warp) * KSEL + lane];
        u64 hmax = __shfl_sync(0xffffffffu, h2, 31);
        int b = b0 + warp + NWRP;
        u64 e = (b < b0 + GSZ) ? g_btop[b * KSEL + lane] : ~0ull;
        for (; b < b0 + GSZ; b += NWRP) {
            const int bn = b + NWRP;
            const u64 e_next = (bn < b0 + GSZ) ? g_btop[bn * KSEL + lane] : ~0ull;
            const u64 bmin = __shfl_sync(0xffffffffu, e, 0);
            if (bmin < hmax) {
                h2 = merge_sorted(h2, e, lane);
                hmax = __shfl_sync(0xffffffffu, h2, 31);
            }
            e = e_next;
        }
        s_lists[warp][lane] = h2;
        float z = 0.0f;
        for (int i = tid; i < GSZ; i += T1) z += g_bz[b0 + i];
        #pragma unroll
        for (int off = 16; off; off >>= 1) z += __shfl_xor_sync(0xffffffffu, z, off);
        if (lane == 0) s_z[warp] = z;
        __syncthreads();
        if (warp == 0) {
            u64 a = s_lists[0][lane];
            #pragma unroll
            for (int w = 1; w < NWRP; w++) a = merge_sorted(a, s_lists[w][lane], lane);
            g_gtop[gid * KSEL + lane] = a;
            if (lane == 0) {
                float zz = 0.0f;
                #pragma unroll
                for (int w = 0; w < NWRP; w++) zz += s_z[w];
                g_gz[gid] = zz;
            }
        }
    }

    // ---- tier-2 election: last of the 12 group-finishers ----
    __threadfence();
    __syncthreads();
    if (tid == 0) amLast2 = (atomicAdd(&g_c2, 1) == NGRP - 1);
    __syncthreads();
    if (!amLast2) return;
    if (tid == 0) g_c2 = 0;

    {   // merge 12 group lists (warps take 0..3, then 4..11)
        u64 h3 = g_gtop[warp * KSEL + lane];
        #pragma unroll
        for (int g = NWRP; g < NGRP; g += NWRP) {
            const int gi = g + warp;
            if (gi < NGRP) h3 = merge_sorted(h3, g_gtop[gi * KSEL + lane], lane);
        }
        s_lists[warp][lane] = h3;
        float z = 0.0f;
        for (int i = tid; i < NGRP; i += T1) z += g_gz[i];
        #pragma unroll
        for (int off = 16; off; off >>= 1) z += __shfl_xor_sync(0xffffffffu, z, off);
        if (lane == 0) s_z[warp] = z;
        __syncthreads();
        if (warp == 0) {
            u64 a = s_lists[0][lane];
            #pragma unroll
            for (int w = 1; w < NWRP; w++) a = merge_sorted(a, s_lists[w][lane], lane);
            if (a == ~0ull) { wv[lane] = 0.0f; iv[lane] = 0; }
            else {
                wv[lane] = __expf(-__uint_as_float((u32)(a >> 32)));
                iv[lane] = (int)(u32)a;
            }
            if (lane == 0) {
                float t2 = 0.0f;
                #pragma unroll
                for (int w = 0; w < NWRP; w++) t2 += s_z[w];
                zinv_s = 1.0f / t2;
            }
        }
        __syncthreads();
        if (tid < DIMS) {
            float acc = 0.0f;
            #pragma unroll
            for (int k = 0; k < KSEL; k++)
                acc += wv[k] * __ldg(Y + (size_t)iv[k] * DIMS + tid);
            out[tid] = acc * zinv_s;
        }
    }
}

extern "C" void kernel_launch(void* const* d_in, const int* in_sizes, int n_in,
                              void* d_out, int out_size) {
    const float* X = (const float*)d_in[0];
    const float* Y = (const float*)d_in[1];
    const float* q = (const float*)d_in[2];
    float* out = (float*)d_out;
    const int N = in_sizes[0] / DIMS;

    const int smemBytes = (NWRP * 2 * WTILE_F4 + 16) * (int)sizeof(float4); // ~68.3KB
    cudaFuncSetAttribute(knn_fused, cudaFuncAttributeMaxDynamicSharedMemorySize,
                         smemBytes);
    knn_fused<<<NBLK, T1, smemBytes>>>(X, Y, q, out, N);
}

// round 15
// speedup vs baseline: 2.4826x; 1.0312x over previous
#include <cuda_runtime.h>
#include <math_constants.h>

// D_KNN soft-kNN imputation — persistent kernel, depth-3 per-warp pipelines.
//   inputs: X_train [N,64] f32, y_train [N,64] f32, X_missing [64] f32
//   output: [1,64] f32
//
// 296 blocks (2/SM) x 128 threads. Each WARP owns a private TRIPLE-buffered
// 32-row (8.7KB) cp.async stream with wait_group 2: two tiles always in
// flight during compute. Peeled tail (wait_group 1/0) so every compute is
// provably ordered after its tile lands. One thread = one row from padded
// smem. Selection: threshold + per-warp smem candidate buffer, bitonic flush.
// Two-tier last-block election merges 296 sorted lists.

#define NBLK 296
#define T1   128
#define NWRP 4
#define GSZ  37                  // tier-1 group size (296 = 8*37)
#define NGRP 8
#define KSEL 32
#define DIMS 64
#define WROWS 32                 // rows per warp-tile
#define PADF4 17                 // float4s per row (bank-conflict-free)
#define WTILE_F4 (WROWS * PADF4) // 544 float4s = 8704 B

typedef unsigned long long u64;
typedef unsigned int u32;

__device__ u64   g_btop[NBLK * KSEL];
__device__ float g_bz[NBLK];
__device__ u64   g_gtop[NGRP * KSEL];
__device__ float g_gz[NGRP];
__device__ int   g_c1[NGRP];     // tier-1 counters (zero-init, self-reset)
__device__ int   g_c2 = 0;       // tier-2 counter

// ---- warp-collective helpers ----

__device__ __forceinline__ u64 bsort32(u64 key, int lane) {
    #pragma unroll
    for (int k = 2; k <= 32; k <<= 1) {
        #pragma unroll
        for (int j = k >> 1; j; j >>= 1) {
            u64 p = __shfl_xor_sync(0xffffffffu, key, j);
            bool keepMin = (((lane & j) == 0) == ((lane & k) == 0));
            key = keepMin ? (key < p ? key : p) : (key > p ? key : p);
        }
    }
    return key;
}

__device__ __forceinline__ u64 bmerge32(u64 key, int lane) {
    #pragma unroll
    for (int j = 16; j; j >>= 1) {
        u64 p = __shfl_xor_sync(0xffffffffu, key, j);
        key = ((lane & j) == 0) ? (key < p ? key : p) : (key > p ? key : p);
    }
    return key;
}

// Merge two sorted ascending 32-lists -> sorted 32 smallest of the union.
__device__ __forceinline__ u64 merge_sorted(u64 a, u64 b, int lane) {
    u64 br = __shfl_sync(0xffffffffu, b, 31 - lane);
    a = (a < br) ? a : br;
    return bmerge32(a, lane);
}

// Flush warp candidate buffer (n <= 63) into sorted 'held'; refresh mhi.
__device__ __forceinline__ void flush_cands(volatile u64* wbuf, volatile int* wcnt,
                                            u64& held, u32& mhi, int lane) {
    __syncwarp();
    const int n = *wcnt;
    u64 c = (lane < n) ? wbuf[lane] : ~0ull;
    c = bsort32(c, lane);
    held = merge_sorted(held, c, lane);
    if (n > 32) {
        u64 c2 = (32 + lane < n) ? wbuf[32 + lane] : ~0ull;
        c2 = bsort32(c2, lane);
        held = merge_sorted(held, c2, lane);
    }
    __syncwarp();
    if (lane == 0) *wcnt = 0;
    __syncwarp();
    mhi = (u32)(__shfl_sync(0xffffffffu, held, 31) >> 32);
}

// ---- per-warp cp.async loader: 16 x 16B per thread, 512B-contiguous ops ----

__device__ __forceinline__ void issue_wtile(const float* __restrict__ X,
                                            int rowBase, float4* buf,
                                            int lane, int N) {
    const u32 dstBase = (u32)__cvta_generic_to_shared(buf);
    const int c4 = lane & 15;
    const int h  = lane >> 4;
    #pragma unroll
    for (int k = 0; k < 16; k++) {
        const int rit = 2 * k + h;
        const float4* src = (const float4*)X
                          + (size_t)min(rowBase + rit, N - 1) * 16 + c4;
        const u32 dst = dstBase + (u32)(rit * PADF4 + c4) * 16u;
        asm volatile("cp.async.cg.shared.global [%0], [%1], 16;\n"
                     :: "r"(dst), "l"(src));
    }
}

// ---- one tile's distance + selection work (thread = one row) ----

__device__ __forceinline__ void compute_tile(const float4* buf, const float4* qs,
                                             int t, int lane, int warp, int N,
                                             float& wsum, u64& held, u32& mhi,
                                             u64 (*wbuf)[64], int* wcnt) {
    const int grow = t * WROWS + lane;
    const float4* rp = buf + lane * PADF4;
    float s0 = 0.f, s1 = 0.f, s2 = 0.f, s3 = 0.f;
    #pragma unroll
    for (int k = 0; k < 16; k++) {
        const float4 x = rp[k];
        const float4 qq = qs[k];
        float d;
        d = x.x - qq.x; s0 = fmaf(d, d, s0);
        d = x.y - qq.y; s1 = fmaf(d, d, s1);
        d = x.z - qq.z; s2 = fmaf(d, d, s2);
        d = x.w - qq.w; s3 = fmaf(d, d, s3);
    }
    float dist = sqrtf((s0 + s1) + (s2 + s3));
    if (grow >= N) dist = CUDART_INF_F;
    wsum += __expf(-dist);                   // exp(-inf) = 0 for OOB
    const u32 db = __float_as_uint(dist);

    if (db < mhi && grow < N) {
        const int p = atomicAdd(&wcnt[warp], 1);
        wbuf[warp][p] = ((u64)db << 32) | (u32)grow;
    }
    __syncwarp();
    if (wcnt[warp] >= 32)                    // warp-uniform; rare
        flush_cands(wbuf[warp], &wcnt[warp], held, mhi, lane);
}

__global__ void __launch_bounds__(T1)
knn_fused(const float* __restrict__ X, const float* __restrict__ Y,
          const float* __restrict__ q, float* __restrict__ out, int N) {
    extern __shared__ float4 smem[];     // [NWRP][3][WTILE_F4] + qs[16]
    float4* qs = smem + NWRP * 3 * WTILE_F4;

    __shared__ u64 s_lists[NWRP][KSEL];
    __shared__ u64 wbuf[NWRP][64];
    __shared__ int wcnt[NWRP];
    __shared__ float s_z[NWRP];
    __shared__ float wv[KSEL];
    __shared__ int   iv[KSEL];
    __shared__ float zinv_s;
    __shared__ int amLast1, amLast2;

    const int tid  = threadIdx.x;
    const int lane = tid & 31;
    const int warp = tid >> 5;
    const int tiles = (N + WROWS - 1) / WROWS;
    const int gw = blockIdx.x * NWRP + warp;
    const int stride = NBLK * NWRP;

    if (tid < 16) qs[tid] = __ldg((const float4*)q + tid);
    if (tid < NWRP) wcnt[tid] = 0;
    __syncthreads();

    float4* mybuf = smem + warp * 3 * WTILE_F4;

    // prologue: up to 2 tiles in flight (one commit group each)
    if (gw < tiles) {
        issue_wtile(X, gw * WROWS, mybuf, lane, N);
        asm volatile("cp.async.commit_group;\n" ::: "memory");
    }
    if (gw + stride < tiles) {
        issue_wtile(X, (gw + stride) * WROWS, mybuf + WTILE_F4, lane, N);
        asm volatile("cp.async.commit_group;\n" ::: "memory");
    }

    u64 held = ~0ull;                    // sorted-ascending invariant
    u32 mhi  = 0xFFFFFFFFu;
    float wsum = 0.0f;
    int cur = 0;
    int t = gw;

    // main loop: exactly 3 real groups pending at each wait -> wait_group 2
    // provably completes tile t before its compute.
    for (; t + 2 * stride < tiles; t += stride) {
        const int nxt = (cur >= 1) ? cur - 1 : cur + 2;   // (cur+2)%3
        issue_wtile(X, (t + 2 * stride) * WROWS, mybuf + nxt * WTILE_F4, lane, N);
        asm volatile("cp.async.commit_group;\n" ::: "memory");
        asm volatile("cp.async.wait_group 2;\n" ::: "memory");
        __syncwarp();
        compute_tile(mybuf + cur * WTILE_F4, qs, t, lane, warp, N,
                     wsum, held, mhi, wbuf, wcnt);
        cur = (cur < 2) ? cur + 1 : 0;
    }
    // peeled tail: 1 or 2 tiles already in flight
    if (t < tiles) {
        if (t + stride < tiles) {
            asm volatile("cp.async.wait_group 1;\n" ::: "memory");
            __syncwarp();
            compute_tile(mybuf + cur * WTILE_F4, qs, t, lane, warp, N,
                         wsum, held, mhi, wbuf, wcnt);
            cur = (cur < 2) ? cur + 1 : 0;
            asm volatile("cp.async.wait_group 0;\n" ::: "memory");
            __syncwarp();
            compute_tile(mybuf + cur * WTILE_F4, qs, t + stride, lane, warp, N,
                         wsum, held, mhi, wbuf, wcnt);
        } else {
            asm volatile("cp.async.wait_group 0;\n" ::: "memory");
            __syncwarp();
            compute_tile(mybuf + cur * WTILE_F4, qs, t, lane, warp, N,
                         wsum, held, mhi, wbuf, wcnt);
        }
    }
    if (wcnt[warp] > 0)
        flush_cands(wbuf[warp], &wcnt[warp], held, mhi, lane);

    // ---- per-block epilogue: sorted top-32 + partial Z ----
    s_lists[warp][lane] = held;
    #pragma unroll
    for (int off = 16; off; off >>= 1) wsum += __shfl_xor_sync(0xffffffffu, wsum, off);
    if (lane == 0) s_z[warp] = wsum;
    __syncthreads();

    if (warp == 0) {
        u64 a = s_lists[0][lane];
        #pragma unroll
        for (int w = 1; w < NWRP; w++) a = merge_sorted(a, s_lists[w][lane], lane);
        g_btop[blockIdx.x * KSEL + lane] = a;
        if (lane == 0) {
            float z = 0.0f;
            #pragma unroll
            for (int w = 0; w < NWRP; w++) z += s_z[w];
            g_bz[blockIdx.x] = z;
        }
    }

    // ---- tier-1 election: last block of each 37-block group ----
    const int gid = blockIdx.x / GSZ;
    const int b0  = gid * GSZ;
    __threadfence();
    __syncthreads();
    if (tid == 0) amLast1 = (atomicAdd(&g_c1[gid], 1) == GSZ - 1);
    __syncthreads();
    if (!amLast1) return;
    if (tid == 0) g_c1[gid] = 0;

    {   // merge this group's 37 sorted lists (4 warps, ~9 each, 1-compare skip)
        u64 h2 = g_btop[(b0 + warp) * KSEL + lane];
        u64 hmax = __shfl_sync(0xffffffffu, h2, 31);
        int b = b0 + warp + NWRP;
        u64 e = (b < b0 + GSZ) ? g_btop[b * KSEL + lane] : ~0ull;
        for (; b < b0 + GSZ; b += NWRP) {
            const int bn = b + NWRP;
            const u64 e_next = (bn < b0 + GSZ) ? g_btop[bn * KSEL + lane] : ~0ull;
            const u64 bmin = __shfl_sync(0xffffffffu, e, 0);
            if (bmin < hmax) {
                h2 = merge_sorted(h2, e, lane);
                hmax = __shfl_sync(0xffffffffu, h2, 31);
            }
            e = e_next;
        }
        s_lists[warp][lane] = h2;
        float z = 0.0f;
        for (int i = tid; i < GSZ; i += T1) z += g_bz[b0 + i];
        #pragma unroll
        for (int off = 16; off; off >>= 1) z += __shfl_xor_sync(0xffffffffu, z, off);
        if (lane == 0) s_z[warp] = z;
        __syncthreads();
        if (warp == 0) {
            u64 a = s_lists[0][lane];
            #pragma unroll
            for (int w = 1; w < NWRP; w++) a = merge_sorted(a, s_lists[w][lane], lane);
            g_gtop[gid * KSEL + lane] = a;
            if (lane == 0) {
                float zz = 0.0f;
                #pragma unroll
                for (int w = 0; w < NWRP; w++) zz += s_z[w];
                g_gz[gid] = zz;
            }
        }
    }

    // ---- tier-2 election: last of the 8 group-finishers ----
    __threadfence();
    __syncthreads();
    if (tid == 0) amLast2 = (atomicAdd(&g_c2, 1) == NGRP - 1);
    __syncthreads();
    if (!amLast2) return;
    if (tid == 0) g_c2 = 0;

    {   // merge 8 group lists (one per warp, then 4-way tree in warp 0)
        u64 h3 = g_gtop[warp * KSEL + lane];
        const int gi = warp + NWRP;
        if (gi < NGRP) h3 = merge_sorted(h3, g_gtop[gi * KSEL + lane], lane);
        s_lists[warp][lane] = h3;
        float z = 0.0f;
        for (int i = tid; i < NGRP; i += T1) z += g_gz[i];
        #pragma unroll
        for (int off = 16; off; off >>= 1) z += __shfl_xor_sync(0xffffffffu, z, off);
        if (lane == 0) s_z[warp] = z;
        __syncthreads();
        if (warp == 0) {
            u64 a = s_lists[0][lane];
            #pragma unroll
            for (int w = 1; w < NWRP; w++) a = merge_sorted(a, s_lists[w][lane], lane);
            if (a == ~0ull) { wv[lane] = 0.0f; iv[lane] = 0; }
            else {
                wv[lane] = __expf(-__uint_as_float((u32)(a >> 32)));
                iv[lane] = (int)(u32)a;
            }
            if (lane == 0) {
                float t2 = 0.0f;
                #pragma unroll
                for (int w = 0; w < NWRP; w++) t2 += s_z[w];
                zinv_s = 1.0f / t2;
            }
        }
        __syncthreads();
        if (tid < DIMS) {
            float acc = 0.0f;
            #pragma unroll
            for (int k = 0; k < KSEL; k++)
                acc += wv[k] * __ldg(Y + (size_t)iv[k] * DIMS + tid);
            out[tid] = acc * zinv_s;
        }
    }
}

extern "C" void kernel_launch(void* const* d_in, const int* in_sizes, int n_in,
                              void* d_out, int out_size) {
    const float* X = (const float*)d_in[0];
    const float* Y = (const float*)d_in[1];
    const float* q = (const float*)d_in[2];
    float* out = (float*)d_out;
    const int N = in_sizes[0] / DIMS;

    const int smemBytes = (NWRP * 3 * WTILE_F4 + 16) * (int)sizeof(float4); // ~102.2KB
    cudaFuncSetAttribute(knn_fused, cudaFuncAttributeMaxDynamicSharedMemorySize,
                         smemBytes);
    knn_fused<<<NBLK, T1, smemBytes>>>(X, Y, q, out, N);
}